// round 6
// baseline (speedup 1.0000x reference)
#include <cuda_runtime.h>
#include <cstdint>

// ---------------- problem constants ----------------
#define SQ   4096
#define BB   8
#define HID  1024
#define KTOT 1024
#define MTOT (SQ*BB)          // 32768
#define NTOT (3*HID)          // 3072
#define BH   (BB*HID)         // 8192
#define GSZ  ((size_t)MTOT*HID)

// ---------------- GEMM tiling ----------------
#define BM   128
#define BN   256
#define BK   32
#define NCHK (KTOT/BK)        // 32
#define NSTG 3
#define STRD 36               // padded row stride (floats): conflict-free ldmatrix
#define A_BYTES (BM*STRD*4)   // 18432
#define B_BYTES (BN*STRD*4)   // 36864
#define STG_BYTES (A_BYTES + B_BYTES)   // 55296
#define SMEM_TOTAL (NSTG*STG_BYTES)     // 165888

// ---------------- scan chunking ----------------
#define TCH 32
#define NCH (SQ/TCH)          // 128

// ---------------- scratch ----------------
__device__ float    g_gates[3*GSZ];          // Z, F, G planes (activated)
__device__ uint32_t g_xt[(size_t)MTOT*KTOT]; // X as tf32 bits
__device__ uint32_t g_wt[(size_t)NTOT*KTOT]; // W as tf32 bits
__device__ float    g_chA[NCH*BH];
__device__ float    g_chB[NCH*BH];
__device__ float    g_cin[NCH*BH];

// ---------------- PTX helpers ----------------
__device__ __forceinline__ uint32_t smem_u32(const void* p) {
    uint32_t a;
    asm("{ .reg .u64 t; cvta.to.shared.u64 t, %1; cvt.u32.u64 %0, t; }" : "=r"(a) : "l"(p));
    return a;
}
#define CP16(dst, src) \
    asm volatile("cp.async.cg.shared.global [%0], [%1], 16;" :: "r"(dst), "l"(src))

__device__ __forceinline__ uint32_t f2tf32(float x) {
    uint32_t u;
    asm("cvt.rna.tf32.f32 %0, %1;" : "=r"(u) : "f"(x));
    return u;
}
__device__ __forceinline__ void ldsm4(uint32_t* r, uint32_t addr) {
    asm volatile("ldmatrix.sync.aligned.m8n8.x4.shared.b16 {%0,%1,%2,%3}, [%4];"
                 : "=r"(r[0]), "=r"(r[1]), "=r"(r[2]), "=r"(r[3]) : "r"(addr));
}
__device__ __forceinline__ void mma_tf32(float* d, const uint32_t* a, const uint32_t* b) {
    asm volatile(
        "mma.sync.aligned.m16n8k8.row.col.f32.tf32.tf32.f32 "
        "{%0,%1,%2,%3}, {%4,%5,%6,%7}, {%8,%9}, {%0,%1,%2,%3};"
        : "+f"(d[0]), "+f"(d[1]), "+f"(d[2]), "+f"(d[3])
        : "r"(a[0]), "r"(a[1]), "r"(a[2]), "r"(a[3]), "r"(b[0]), "r"(b[1]));
}

// ============================================================================
// Pre-convert fp32 -> tf32 bit patterns (RNA) for X and W in one launch.
// ============================================================================
#define XN4 ((int)((size_t)MTOT*KTOT/4))
#define WN4 ((int)((size_t)NTOT*KTOT/4))
__global__ __launch_bounds__(256) void conv_tf32(const float* __restrict__ X,
                                                 const float* __restrict__ W) {
    int i = blockIdx.x * 256 + threadIdx.x;
    const float4* src;
    uint4* dst;
    int idx;
    if (i < XN4) { src = (const float4*)X; dst = (uint4*)g_xt; idx = i; }
    else if (i < XN4 + WN4) { src = (const float4*)W; dst = (uint4*)g_wt; idx = i - XN4; }
    else return;
    float4 v = src[idx];
    uint4 o;
    o.x = f2tf32(v.x); o.y = f2tf32(v.y); o.z = f2tf32(v.z); o.w = f2tf32(v.w);
    dst[idx] = o;
}

// ============================================================================
// tf32 mma.sync GEMM (pre-converted inputs) + fused activations.
// CTA tile 128x256, 512 threads (16 warps: 4m x 4n), warp tile 32x64.
// 3-stage cp.async pipeline.
// ============================================================================
__global__ __launch_bounds__(512, 1) void gemm_mma(const float* __restrict__ bias) {
    extern __shared__ uint32_t smem[];
    const uint32_t sb = smem_u32(smem);
    const int tid = threadIdx.x;
    const int wid = tid >> 5;
    const int lid = tid & 31;
    const int m0 = blockIdx.y * BM;
    const int n0 = blockIdx.x * BN;

    const int warp_m = (wid & 3) * 32;     // 0,32,64,96
    const int warp_n = (wid >> 2) * 64;    // 0,64,128,192

    const uint32_t* Xb = g_xt + (size_t)m0 * KTOT;
    const uint32_t* Wb = g_wt + (size_t)n0 * KTOT;

    float acc[2][8][4];
#pragma unroll
    for (int mf = 0; mf < 2; mf++)
#pragma unroll
        for (int nf = 0; nf < 8; nf++)
#pragma unroll
            for (int q = 0; q < 4; q++) acc[mf][nf][q] = 0.f;

    auto load_chunk = [&](int c, int s) {
        const uint32_t abase = sb + s * STG_BYTES;
        const uint32_t bbase = abase + A_BYTES;
        const int kc = c * BK;
#pragma unroll
        for (int p = 0; p < 2; p++) {            // A: 128 rows x 8 segs = 1024
            int seg = tid + p * 512;
            int row = seg >> 3, ks = seg & 7;
            CP16(abase + row * (STRD * 4) + ks * 16,
                 Xb + (size_t)row * KTOT + kc + ks * 4);
        }
#pragma unroll
        for (int p = 0; p < 4; p++) {            // B: 256 rows x 8 segs = 2048
            int seg = tid + p * 512;
            int row = seg >> 3, ks = seg & 7;
            CP16(bbase + row * (STRD * 4) + ks * 16,
                 Wb + (size_t)row * KTOT + kc + ks * 4);
        }
        asm volatile("cp.async.commit_group;" ::: "memory");
    };

    load_chunk(0, 0);
    load_chunk(1, 1);
    load_chunk(2, 2);

    // ldmatrix per-thread source rows
    const int a_row = (lid & 7) + 8 * ((lid >> 3) & 1);
    const int a_kq  = 4 * (lid >> 4);
    const int b_row = (lid & 7) + 8 * (lid >> 4);
    const int b_kq  = 4 * ((lid >> 3) & 1);

    for (int i = 0; i < NCHK; i++) {
        const int s = i % NSTG;
        if      (i < NCHK - 2) asm volatile("cp.async.wait_group 2;" ::: "memory");
        else if (i < NCHK - 1) asm volatile("cp.async.wait_group 1;" ::: "memory");
        else                   asm volatile("cp.async.wait_group 0;" ::: "memory");
        __syncthreads();

        const uint32_t abase = sb + s * STG_BYTES;
        const uint32_t bbase = abase + A_BYTES;
        const uint32_t aaddr = abase + (warp_m + a_row) * (STRD * 4) + a_kq * 4;
        const uint32_t baddr = bbase + (warp_n + b_row) * (STRD * 4) + b_kq * 4;

#pragma unroll
        for (int k8 = 0; k8 < 4; k8++) {
            const int kk = k8 * 32;
            uint32_t af[2][4];
            ldsm4(af[0], aaddr + kk);
            ldsm4(af[1], aaddr + 16 * (STRD * 4) + kk);
            uint32_t bf[8][2];
#pragma unroll
            for (int np = 0; np < 4; np++)
                ldsm4(bf[2 * np], baddr + np * 16 * (STRD * 4) + kk);
#pragma unroll
            for (int mf = 0; mf < 2; mf++)
#pragma unroll
                for (int nf = 0; nf < 8; nf++)
                    mma_tf32(acc[mf][nf], af[mf], bf[nf]);
        }
        __syncthreads();
        if (i + NSTG < NCHK) load_chunk(i + NSTG, s);
    }

    // ---- epilogue: bias + activation, write gate plane ----
    const int lr = lid >> 2;
    const int lc = lid & 3;
    const int gate  = blockIdx.x >> 2;          // 4 x-blocks of 256 per gate
    const int hcol0 = (blockIdx.x & 3) * BN;
    float* gout = g_gates + (size_t)gate * GSZ;

#pragma unroll
    for (int mf = 0; mf < 2; mf++) {
#pragma unroll
        for (int nf = 0; nf < 8; nf++) {
            const int ncol = warp_n + nf * 8 + 2 * lc;
            const float b0 = __ldg(&bias[n0 + ncol]);
            const float b1 = __ldg(&bias[n0 + ncol + 1]);
#pragma unroll
            for (int half = 0; half < 2; half++) {
                const int m = m0 + warp_m + mf * 16 + lr + half * 8;
                float y0 = acc[mf][nf][2 * half + 0] + b0;
                float y1 = acc[mf][nf][2 * half + 1] + b1;
                float v0, v1;
                if (gate == 0) {
                    v0 = 2.f / (1.f + __expf(-2.f * y0)) - 1.f;  // tanh
                    v1 = 2.f / (1.f + __expf(-2.f * y1)) - 1.f;
                } else {
                    v0 = 1.f / (1.f + __expf(-y0));              // sigmoid
                    v1 = 1.f / (1.f + __expf(-y1));
                }
                *(float2*)(gout + (size_t)m * HID + hcol0 + ncol) = make_float2(v0, v1);
            }
        }
    }
}

// ============================================================================
// Scan phase A: per-chunk affine composition.
// ============================================================================
__global__ __launch_bounds__(256) void scanA() {
    const int j  = blockIdx.x * 256 + threadIdx.x;
    const int ch = blockIdx.y;
    const float* Zp = g_gates;
    const float* Fp = g_gates + GSZ;

    float A = 1.f, Bv = 0.f;
    size_t base = (size_t)ch * TCH * BH + j;
#pragma unroll 8
    for (int s = 0; s < TCH; s++) {
        size_t idx = base + (size_t)s * BH;
        float f = Fp[idx], z = Zp[idx];
        float omf = 1.f - f;
        A  = A * omf;
        Bv = f * z + omf * Bv;
    }
    g_chA[ch * BH + j] = A;
    g_chB[ch * BH + j] = Bv;
}

// ============================================================================
// Scan phase B: sequential over 128 chunk states; records per-chunk carry.
// ============================================================================
__global__ __launch_bounds__(256) void scanB(const float* __restrict__ hidden,
                                             float* __restrict__ c_last) {
    const int j = blockIdx.x * 256 + threadIdx.x;
    float c = hidden[j];
#pragma unroll 4
    for (int i = 0; i < NCH; i++) {
        g_cin[i * BH + j] = c;
        c = g_chB[i * BH + j] + g_chA[i * BH + j] * c;
    }
    c_last[j] = c;
}

// ============================================================================
// Scan phase C: re-scan chunks with correct carries; write C and H.
// ============================================================================
__global__ __launch_bounds__(256) void scanC(float* __restrict__ Hout,
                                             float* __restrict__ Cout) {
    const int j  = blockIdx.x * 256 + threadIdx.x;
    const int ch = blockIdx.y;
    const float* Zp = g_gates;
    const float* Fp = g_gates + GSZ;
    const float* Gp = g_gates + 2 * GSZ;

    float c = g_cin[ch * BH + j];
    size_t base = (size_t)ch * TCH * BH + j;
#pragma unroll 4
    for (int s = 0; s < TCH; s++) {
        size_t idx = base + (size_t)s * BH;
        float f = Zp[idx], z, g;
        z = f;                       // placeholder to keep load order simple
        f = Fp[idx];
        g = Gp[idx];
        c = f * z + (1.f - f) * c;
        Cout[idx] = c;
        Hout[idx] = g * c;
    }
}

// ============================================================================
// Launch
// ============================================================================
extern "C" void kernel_launch(void* const* d_in, const int* in_sizes, int n_in,
                              void* d_out, int out_size) {
    const float* X      = (const float*)d_in[0];
    const float* hidden = (const float*)d_in[1];
    const float* W      = (const float*)d_in[2];
    const float* bias   = (const float*)d_in[3];

    float* out   = (float*)d_out;
    float* Hout  = out;
    float* Clast = out + GSZ;
    float* Cout  = out + GSZ + BH;

    cudaFuncSetAttribute(gemm_mma, cudaFuncAttributeMaxDynamicSharedMemorySize, SMEM_TOTAL);

    const int ctot = XN4 + WN4;
    conv_tf32<<<(ctot + 255) / 256, 256>>>(X, W);
    gemm_mma<<<dim3(NTOT / BN, MTOT / BM), 512, SMEM_TOTAL>>>(bias);
    scanA<<<dim3(BH / 256, NCH), 256>>>();
    scanB<<<BH / 256, 256>>>(hidden, Clast);
    scanC<<<dim3(BH / 256, NCH), 256>>>(Hout, Cout);
}

// round 7
// speedup vs baseline: 1.1597x; 1.1597x over previous
#include <cuda_runtime.h>
#include <cstdint>

// ---------------- problem constants ----------------
#define SQ   4096
#define BB   8
#define HID  1024
#define KTOT 1024
#define MTOT (SQ*BB)          // 32768
#define NTOT (3*HID)          // 3072
#define BH   (BB*HID)         // 8192
#define GSZ  ((size_t)MTOT*HID)

// ---------------- GEMM tiling ----------------
#define BM   128
#define BN   128
#define BK   32
#define NCHK (KTOT/BK)        // 32
#define NSTG 3
#define STRD 36               // padded row stride (floats): conflict-free ldmatrix
#define A_BYTES (BM*STRD*4)   // 18432
#define B_BYTES (BN*STRD*4)   // 18432
#define STG_BYTES (A_BYTES + B_BYTES)   // 36864
#define SMEM_TOTAL (NSTG*STG_BYTES)     // 110592 -> 2 CTA/SM

// ---------------- scan chunking ----------------
#define TCH 128
#define NCH (SQ/TCH)          // 32

// ---------------- scratch ----------------
__device__ float    g_gates[3*GSZ];          // Z, F, G planes (activated)
__device__ uint32_t g_xt[(size_t)MTOT*KTOT]; // X as tf32 bits
__device__ uint32_t g_wt[(size_t)NTOT*KTOT]; // W as tf32 bits
__device__ float    g_chA[NCH*BH];
__device__ float    g_chB[NCH*BH];
__device__ float    g_cin[NCH*BH];

// ---------------- PTX helpers ----------------
__device__ __forceinline__ uint32_t smem_u32(const void* p) {
    uint32_t a;
    asm("{ .reg .u64 t; cvta.to.shared.u64 t, %1; cvt.u32.u64 %0, t; }" : "=r"(a) : "l"(p));
    return a;
}
#define CP16(dst, src) \
    asm volatile("cp.async.cg.shared.global [%0], [%1], 16;" :: "r"(dst), "l"(src))

__device__ __forceinline__ uint32_t f2tf32(float x) {
    uint32_t u;
    asm("cvt.rna.tf32.f32 %0, %1;" : "=r"(u) : "f"(x));
    return u;
}
__device__ __forceinline__ void ldsm4(uint32_t* r, uint32_t addr) {
    asm volatile("ldmatrix.sync.aligned.m8n8.x4.shared.b16 {%0,%1,%2,%3}, [%4];"
                 : "=r"(r[0]), "=r"(r[1]), "=r"(r[2]), "=r"(r[3]) : "r"(addr));
}
__device__ __forceinline__ void mma_tf32(float* d, const uint32_t* a, const uint32_t* b) {
    asm volatile(
        "mma.sync.aligned.m16n8k8.row.col.f32.tf32.tf32.f32 "
        "{%0,%1,%2,%3}, {%4,%5,%6,%7}, {%8,%9}, {%0,%1,%2,%3};"
        : "+f"(d[0]), "+f"(d[1]), "+f"(d[2]), "+f"(d[3])
        : "r"(a[0]), "r"(a[1]), "r"(a[2]), "r"(a[3]), "r"(b[0]), "r"(b[1]));
}

// ============================================================================
// Pre-convert fp32 -> tf32 bit patterns (RNA) for X and W in one launch.
// ============================================================================
#define XN4 ((int)((size_t)MTOT*KTOT/4))
#define WN4 ((int)((size_t)NTOT*KTOT/4))
__global__ __launch_bounds__(256) void conv_tf32(const float* __restrict__ X,
                                                 const float* __restrict__ W) {
    int i = blockIdx.x * 256 + threadIdx.x;
    const float4* src;
    uint4* dst;
    int idx;
    if (i < XN4) { src = (const float4*)X; dst = (uint4*)g_xt; idx = i; }
    else if (i < XN4 + WN4) { src = (const float4*)W; dst = (uint4*)g_wt; idx = i - XN4; }
    else return;
    float4 v = src[idx];
    uint4 o;
    o.x = f2tf32(v.x); o.y = f2tf32(v.y); o.z = f2tf32(v.z); o.w = f2tf32(v.w);
    dst[idx] = o;
}

// ============================================================================
// tf32 mma.sync GEMM (pre-converted inputs) + fused activations.
// CTA tile 128x128, 256 threads (8 warps: 4m x 2n), warp tile 32x64.
// 3-stage cp.async ring, ONE __syncthreads per iteration.
// ============================================================================
__global__ __launch_bounds__(256, 2) void gemm_mma(const float* __restrict__ bias) {
    extern __shared__ uint32_t smem[];
    const uint32_t sb = smem_u32(smem);
    const int tid = threadIdx.x;
    const int wid = tid >> 5;
    const int lid = tid & 31;
    const int m0 = blockIdx.y * BM;
    const int n0 = blockIdx.x * BN;

    const int warp_m = (wid & 3) * 32;     // 0,32,64,96
    const int warp_n = (wid >> 2) * 64;    // 0,64

    const uint32_t* Xb = g_xt + (size_t)m0 * KTOT;
    const uint32_t* Wb = g_wt + (size_t)n0 * KTOT;

    float acc[2][8][4];
#pragma unroll
    for (int mf = 0; mf < 2; mf++)
#pragma unroll
        for (int nf = 0; nf < 8; nf++)
#pragma unroll
            for (int q = 0; q < 4; q++) acc[mf][nf][q] = 0.f;

    auto load_chunk = [&](int c, int s) {
        const uint32_t abase = sb + s * STG_BYTES;
        const uint32_t bbase = abase + A_BYTES;
        const int kc = c * BK;
#pragma unroll
        for (int p = 0; p < 4; p++) {
            int seg = tid + p * 256;
            int row = seg >> 3, ks = seg & 7;
            CP16(abase + row * (STRD * 4) + ks * 16,
                 Xb + (size_t)row * KTOT + kc + ks * 4);
        }
#pragma unroll
        for (int p = 0; p < 4; p++) {
            int seg = tid + p * 256;
            int row = seg >> 3, ks = seg & 7;
            CP16(bbase + row * (STRD * 4) + ks * 16,
                 Wb + (size_t)row * KTOT + kc + ks * 4);
        }
        asm volatile("cp.async.commit_group;" ::: "memory");
    };

    // prologue: stages 0,1 in flight
    load_chunk(0, 0);
    load_chunk(1, 1);

    // ldmatrix per-thread source rows
    const int a_row = (lid & 7) + 8 * ((lid >> 3) & 1);
    const int a_kq  = 4 * (lid >> 4);
    const int b_row = (lid & 7) + 8 * (lid >> 4);
    const int b_kq  = 4 * ((lid >> 3) & 1);

    for (int i = 0; i < NCHK; i++) {
        const int s = i % NSTG;
        // chunk i must be resident
        if (i < NCHK - 2) asm volatile("cp.async.wait_group 1;" ::: "memory");
        else              asm volatile("cp.async.wait_group 0;" ::: "memory");
        __syncthreads();

        // issue loads for chunk i+2 into slot (i+2)%3 — that slot's readers
        // (compute of iter i-1) finished before the sync above.
        if (i + 2 < NCHK) load_chunk(i + 2, (i + 2) % NSTG);

        const uint32_t abase = sb + s * STG_BYTES;
        const uint32_t bbase = abase + A_BYTES;
        const uint32_t aaddr = abase + (warp_m + a_row) * (STRD * 4) + a_kq * 4;
        const uint32_t baddr = bbase + (warp_n + b_row) * (STRD * 4) + b_kq * 4;

#pragma unroll
        for (int k8 = 0; k8 < 4; k8++) {
            const int kk = k8 * 32;
            uint32_t af[2][4];
            ldsm4(af[0], aaddr + kk);
            ldsm4(af[1], aaddr + 16 * (STRD * 4) + kk);
            uint32_t bf[8][2];
#pragma unroll
            for (int np = 0; np < 4; np++)
                ldsm4(bf[2 * np], baddr + np * 16 * (STRD * 4) + kk);
#pragma unroll
            for (int mf = 0; mf < 2; mf++)
#pragma unroll
                for (int nf = 0; nf < 8; nf++)
                    mma_tf32(acc[mf][nf], af[mf], bf[nf]);
        }
    }

    // ---- epilogue: bias + activation, write gate plane ----
    const int lr = lid >> 2;
    const int lc = lid & 3;
    const int gate  = blockIdx.x >> 3;          // 8 x-blocks of 128 per gate
    const int hcol0 = (blockIdx.x & 7) * BN;
    float* gout = g_gates + (size_t)gate * GSZ;

#pragma unroll
    for (int mf = 0; mf < 2; mf++) {
#pragma unroll
        for (int nf = 0; nf < 8; nf++) {
            const int ncol = warp_n + nf * 8 + 2 * lc;
            const float b0 = __ldg(&bias[n0 + ncol]);
            const float b1 = __ldg(&bias[n0 + ncol + 1]);
#pragma unroll
            for (int half = 0; half < 2; half++) {
                const int m = m0 + warp_m + mf * 16 + lr + half * 8;
                float y0 = acc[mf][nf][2 * half + 0] + b0;
                float y1 = acc[mf][nf][2 * half + 1] + b1;
                float v0, v1;
                if (gate == 0) {
                    v0 = 2.f / (1.f + __expf(-2.f * y0)) - 1.f;  // tanh
                    v1 = 2.f / (1.f + __expf(-2.f * y1)) - 1.f;
                } else {
                    v0 = 1.f / (1.f + __expf(-y0));              // sigmoid
                    v1 = 1.f / (1.f + __expf(-y1));
                }
                *(float2*)(gout + (size_t)m * HID + hcol0 + ncol) = make_float2(v0, v1);
            }
        }
    }
}

// ============================================================================
// Scan phase A: per-chunk affine composition (chunk = 128 steps).
// ============================================================================
__global__ __launch_bounds__(256) void scanA() {
    const int j  = blockIdx.x * 256 + threadIdx.x;
    const int ch = blockIdx.y;
    const float* Zp = g_gates;
    const float* Fp = g_gates + GSZ;

    float A = 1.f, Bv = 0.f;
    size_t base = (size_t)ch * TCH * BH + j;
#pragma unroll 8
    for (int s = 0; s < TCH; s++) {
        size_t idx = base + (size_t)s * BH;
        float f = Fp[idx], z = Zp[idx];
        float omf = 1.f - f;
        A  = A * omf;
        Bv = f * z + omf * Bv;
    }
    g_chA[ch * BH + j] = A;
    g_chB[ch * BH + j] = Bv;
}

// ============================================================================
// Scan phase B: sequential over 32 chunk states; records per-chunk carry.
// ============================================================================
__global__ __launch_bounds__(256) void scanB(const float* __restrict__ hidden,
                                             float* __restrict__ c_last) {
    const int j = blockIdx.x * 256 + threadIdx.x;
    float c = hidden[j];
#pragma unroll 8
    for (int i = 0; i < NCH; i++) {
        g_cin[i * BH + j] = c;
        c = g_chB[i * BH + j] + g_chA[i * BH + j] * c;
    }
    c_last[j] = c;
}

// ============================================================================
// Scan phase C: re-scan chunks with correct carries; write C and H.
// ============================================================================
__global__ __launch_bounds__(256) void scanC(float* __restrict__ Hout,
                                             float* __restrict__ Cout) {
    const int j  = blockIdx.x * 256 + threadIdx.x;
    const int ch = blockIdx.y;
    const float* Zp = g_gates;
    const float* Fp = g_gates + GSZ;
    const float* Gp = g_gates + 2 * GSZ;

    float c = g_cin[ch * BH + j];
    size_t base = (size_t)ch * TCH * BH + j;
#pragma unroll 4
    for (int s = 0; s < TCH; s++) {
        size_t idx = base + (size_t)s * BH;
        float f = Fp[idx], z = Zp[idx], g = Gp[idx];
        c = f * z + (1.f - f) * c;
        Cout[idx] = c;
        Hout[idx] = g * c;
    }
}

// ============================================================================
// Launch
// ============================================================================
extern "C" void kernel_launch(void* const* d_in, const int* in_sizes, int n_in,
                              void* d_out, int out_size) {
    const float* X      = (const float*)d_in[0];
    const float* hidden = (const float*)d_in[1];
    const float* W      = (const float*)d_in[2];
    const float* bias   = (const float*)d_in[3];

    float* out   = (float*)d_out;
    float* Hout  = out;
    float* Clast = out + GSZ;
    float* Cout  = out + GSZ + BH;

    cudaFuncSetAttribute(gemm_mma, cudaFuncAttributeMaxDynamicSharedMemorySize, SMEM_TOTAL);

    const int ctot = XN4 + WN4;
    conv_tf32<<<(ctot + 255) / 256, 256>>>(X, W);
    gemm_mma<<<dim3(NTOT / BN, MTOT / BM), 256, SMEM_TOTAL>>>(bias);
    scanA<<<dim3(BH / 256, NCH), 256>>>();
    scanB<<<BH / 256, 256>>>(hidden, Clast);
    scanC<<<dim3(BH / 256, NCH), 256>>>(Hout, Cout);
}